// round 1
// baseline (speedup 1.0000x reference)
#include <cuda_runtime.h>
#include <math.h>

// Problem constants
#define Bsz   256
#define Tsz   512
#define Isz   300
#define Hsz   128
#define G4    512           // 4*H
#define Msz   (Bsz*Tsz)     // 131072

// Scratch for precomputed input gates: [B,T,4H] fp32 = 256 MiB
__device__ float g_xg[(size_t)Msz * G4];

__device__ __forceinline__ float sigmoidf_(float x) {
    return 1.f / (1.f + __expf(-x));
}

// ----------------------------------------------------------------------------
// Kernel 1: xg[m][n] = sum_k x[m][k]*W_ih[n][k] + b_ih[n] + b_hh[n]
// M=131072, N=512, K=300. Tiles: BM=128, BN=64, BK=16, 256 threads, TM=8,TN=4.
// ----------------------------------------------------------------------------
#define BM 128
#define BN 64
#define BK 16
#define TM 8
#define TN 4

__global__ __launch_bounds__(256)
void gemm_xg_kernel(const float* __restrict__ A,   // x as [M,300]
                    const float* __restrict__ W,   // W_ih [512,300]
                    const float* __restrict__ b_ih,
                    const float* __restrict__ b_hh) {
    __shared__ __align__(16) float As[BK][BM + 4];  // stride 132
    __shared__ __align__(16) float Bs[BK][BN + 4];  // stride 68

    const int tid = threadIdx.x;
    const int tx = tid & 15;        // 0..15
    const int ty = tid >> 4;        // 0..15
    const int m0 = blockIdx.x * BM;
    const int n0 = blockIdx.y * BN;
    const int K = Isz;

    float acc[TM][TN];
#pragma unroll
    for (int i = 0; i < TM; ++i)
#pragma unroll
        for (int j = 0; j < TN; ++j) acc[i][j] = 0.f;

    for (int k0 = 0; k0 < K; k0 += BK) {
        // Load A tile: 128x16 = 2048 elems, 8 per thread
#pragma unroll
        for (int i = 0; i < 8; ++i) {
            int idx = i * 256 + tid;
            int m = idx >> 4, k = idx & 15;
            float v = 0.f;
            if (k0 + k < K) v = A[(size_t)(m0 + m) * K + k0 + k];
            As[k][m] = v;
        }
        // Load B tile: 64x16 = 1024 elems, 4 per thread
#pragma unroll
        for (int i = 0; i < 4; ++i) {
            int idx = i * 256 + tid;
            int n = idx >> 4, k = idx & 15;
            float v = 0.f;
            if (k0 + k < K) v = W[(size_t)(n0 + n) * K + k0 + k];
            Bs[k][n] = v;
        }
        __syncthreads();

#pragma unroll
        for (int k = 0; k < BK; ++k) {
            float a[TM], bb[TN];
            const float4* a4 = (const float4*)&As[k][ty * TM];
            float4 av0 = a4[0], av1 = a4[1];
            a[0]=av0.x; a[1]=av0.y; a[2]=av0.z; a[3]=av0.w;
            a[4]=av1.x; a[5]=av1.y; a[6]=av1.z; a[7]=av1.w;
            float4 bv = *(const float4*)&Bs[k][tx * TN];
            bb[0]=bv.x; bb[1]=bv.y; bb[2]=bv.z; bb[3]=bv.w;
#pragma unroll
            for (int i = 0; i < TM; ++i)
#pragma unroll
                for (int j = 0; j < TN; ++j)
                    acc[i][j] += a[i] * bb[j];
        }
        __syncthreads();
    }

    // Epilogue: add combined bias, write to g_xg
    float bias[TN];
#pragma unroll
    for (int j = 0; j < TN; ++j) {
        int n = n0 + tx * TN + j;
        bias[j] = b_ih[n] + b_hh[n];
    }
#pragma unroll
    for (int i = 0; i < TM; ++i) {
        int m = m0 + ty * TM + i;
        float4 v;
        v.x = acc[i][0] + bias[0];
        v.y = acc[i][1] + bias[1];
        v.z = acc[i][2] + bias[2];
        v.w = acc[i][3] + bias[3];
        *(float4*)&g_xg[(size_t)m * G4 + n0 + tx * TN] = v;
    }
}

// ----------------------------------------------------------------------------
// Kernel 2: persistent recurrent LSTM + fused FC.
// Grid: 64 CTAs x 512 threads. CTA cb owns batch rows 4*cb .. 4*cb+3.
// smem: W_hh rows 0..383 (i,f,g gates) padded stride 132 (192KB+),
//       o-gate rows (384..511) streamed from global (L2-hot).
// Per step: thread j computes pre-activation gate j for all 4 rows,
// applies nonlinearity, stores to sG; then thread t=(r,n) updates c (in reg)
// and writes h to sH. Two barriers per step.
// ----------------------------------------------------------------------------
#define ROWS 4
#define WPAD 132

__global__ __launch_bounds__(512)
void lstm_fc_kernel(const float* __restrict__ W_hh,   // [512,128]
                    const float* __restrict__ fc_w,   // [1,128]
                    const float* __restrict__ fc_b,   // [1]
                    float* __restrict__ out) {        // [256]
    extern __shared__ __align__(16) float sm[];
    float* sW = sm;                    // 384 * 132
    float* sH = sm + 384 * WPAD;       // [4][128]
    float* sG = sH + ROWS * Hsz;       // [4][512]

    const int tid = threadIdx.x;       // 0..511
    const int b0 = blockIdx.x * ROWS;

    // Stage W_hh gates i,f,g into smem (padded rows)
    for (int idx = tid; idx < 384 * Hsz; idx += 512) {
        sW[(idx >> 7) * WPAD + (idx & 127)] = W_hh[idx];
    }
    // h0 = 0
    sH[tid] = 0.f;

    const int r2 = tid >> 7;           // phase-2 row
    const int n2 = tid & 127;          // phase-2 hidden index
    float cst = 0.f;                   // cell state owned by this thread

    const float4* wg4 = (const float4*)(W_hh + (size_t)tid * Hsz); // valid if tid>=384
    const float4* wp4 = (const float4*)(sW + tid * WPAD);          // valid if tid<384

    __syncthreads();

    for (int t = 0; t < Tsz; ++t) {
        // Prefetch input-gate contributions for the 4 rows (coalesced over tid)
        float acc0 = g_xg[(((size_t)(b0 + 0)) * Tsz + t) * G4 + tid];
        float acc1 = g_xg[(((size_t)(b0 + 1)) * Tsz + t) * G4 + tid];
        float acc2 = g_xg[(((size_t)(b0 + 2)) * Tsz + t) * G4 + tid];
        float acc3 = g_xg[(((size_t)(b0 + 3)) * Tsz + t) * G4 + tid];

        const float4* h0 = (const float4*)(sH);
        const float4* h1 = (const float4*)(sH + 128);
        const float4* h2 = (const float4*)(sH + 256);
        const float4* h3 = (const float4*)(sH + 384);

        if (tid < 384) {
#pragma unroll
            for (int k = 0; k < 32; ++k) {
                float4 w = wp4[k];
                float4 a = h0[k], b = h1[k], c = h2[k], d = h3[k];
                acc0 += w.x*a.x + w.y*a.y + w.z*a.z + w.w*a.w;
                acc1 += w.x*b.x + w.y*b.y + w.z*b.z + w.w*b.w;
                acc2 += w.x*c.x + w.y*c.y + w.z*c.z + w.w*c.w;
                acc3 += w.x*d.x + w.y*d.y + w.z*d.z + w.w*d.w;
            }
        } else {
#pragma unroll
            for (int k = 0; k < 32; ++k) {
                float4 w = wg4[k];
                float4 a = h0[k], b = h1[k], c = h2[k], d = h3[k];
                acc0 += w.x*a.x + w.y*a.y + w.z*a.z + w.w*a.w;
                acc1 += w.x*b.x + w.y*b.y + w.z*b.z + w.w*b.w;
                acc2 += w.x*c.x + w.y*c.y + w.z*c.z + w.w*c.w;
                acc3 += w.x*d.x + w.y*d.y + w.z*d.z + w.w*d.w;
            }
        }

        // Activation: j<256 sigmoid (i,f), 256..383 tanh (g), >=384 sigmoid (o)
        if (tid >= 256 && tid < 384) {
            acc0 = tanhf(acc0); acc1 = tanhf(acc1);
            acc2 = tanhf(acc2); acc3 = tanhf(acc3);
        } else {
            acc0 = sigmoidf_(acc0); acc1 = sigmoidf_(acc1);
            acc2 = sigmoidf_(acc2); acc3 = sigmoidf_(acc3);
        }
        sG[0 * G4 + tid] = acc0;
        sG[1 * G4 + tid] = acc1;
        sG[2 * G4 + tid] = acc2;
        sG[3 * G4 + tid] = acc3;
        __syncthreads();

        // Phase 2: c/h update. thread -> (r2, n2)
        float iv = sG[r2 * G4 + n2];
        float fv = sG[r2 * G4 + 128 + n2];
        float gv = sG[r2 * G4 + 256 + n2];
        float ov = sG[r2 * G4 + 384 + n2];
        cst = fv * cst + iv * gv;
        sH[r2 * Hsz + n2] = ov * tanhf(cst);
        __syncthreads();
    }

    // Fused FC: out[b] = h_last[b] . fc_w + fc_b
    if (tid < ROWS) {
        float s = 0.f;
#pragma unroll 8
        for (int k = 0; k < Hsz; ++k) s += sH[tid * Hsz + k] * fc_w[k];
        out[b0 + tid] = s + fc_b[0];
    }
}

// ----------------------------------------------------------------------------
// Launch
// ----------------------------------------------------------------------------
extern "C" void kernel_launch(void* const* d_in, const int* in_sizes, int n_in,
                              void* d_out, int out_size) {
    const float* x    = (const float*)d_in[0];   // [256,512,300]
    const float* W_ih = (const float*)d_in[1];   // [512,300]
    const float* W_hh = (const float*)d_in[2];   // [512,128]
    const float* b_ih = (const float*)d_in[3];   // [512]
    const float* b_hh = (const float*)d_in[4];   // [512]
    const float* fc_w = (const float*)d_in[5];   // [1,128]
    const float* fc_b = (const float*)d_in[6];   // [1]
    float* out = (float*)d_out;                  // [256,1]

    // Kernel 1: input projection GEMM into g_xg
    dim3 grid1(Msz / BM, G4 / BN);  // (1024, 8)
    gemm_xg_kernel<<<grid1, 256>>>(x, W_ih, b_ih, b_hh);

    // Kernel 2: persistent recurrence + fused FC
    const int smem_bytes = (384 * WPAD + ROWS * Hsz + ROWS * G4) * sizeof(float); // 212992
    cudaFuncSetAttribute(lstm_fc_kernel,
                         cudaFuncAttributeMaxDynamicSharedMemorySize, smem_bytes);
    lstm_fc_kernel<<<Bsz / ROWS, 512, smem_bytes>>>(W_hh, fc_w, fc_b, out);
}

// round 2
// speedup vs baseline: 1.1720x; 1.1720x over previous
#include <cuda_runtime.h>
#include <math.h>

// Problem constants
#define Bsz   256
#define Tsz   512
#define Isz   300
#define Hsz   128
#define G4    512           // 4*H
#define Msz   (Bsz*Tsz)     // 131072

// Scratch for precomputed input gates: [B,T,4H] fp32 = 256 MiB
__device__ float g_xg[(size_t)Msz * G4];

typedef unsigned long long ull;

__device__ __forceinline__ float sigmoidf_(float x) {
    return 1.f / (1.f + __expf(-x));
}

// Packed fp32x2 helpers (Blackwell FFMA2 path; ptxas may legalize to 2xFFMA,
// in which case perf is unchanged vs scalar)
__device__ __forceinline__ ull pk2(float x) {
    ull r; asm("mov.b64 %0, {%1, %1};" : "=l"(r) : "f"(x)); return r;
}
__device__ __forceinline__ void ffma2(ull& d, ull a, ull b) {
    asm("fma.rn.f32x2 %0, %1, %2, %0;" : "+l"(d) : "l"(a), "l"(b));
}
__device__ __forceinline__ float2 upk(ull v) {
    float2 r; asm("mov.b64 {%0, %1}, %2;" : "=f"(r.x), "=f"(r.y) : "l"(v)); return r;
}

// ----------------------------------------------------------------------------
// Kernel 1: xg[m][n] = sum_k x[m][k]*W_ih[n][k] + b_ih[n] + b_hh[n]
// M=131072, N=512, K=300. BM=128, BN=128, BK=16, 256 thr, TM=8, TN=8 (FFMA2).
// Reg-staged double buffering, one barrier per k-tile.
// ----------------------------------------------------------------------------
#define BM 128
#define BN 128
#define BK 16
#define NTILES 19    // ceil(300/16)
#define APAD 4

__device__ __forceinline__ float4 ldg_guard(const float* __restrict__ p, int col) {
    if (col < Isz) return *(const float4*)(p + col);
    return make_float4(0.f, 0.f, 0.f, 0.f);
}

__global__ __launch_bounds__(256, 2)
void gemm_xg_kernel(const float* __restrict__ A,   // x as [M,300]
                    const float* __restrict__ W,   // W_ih [512,300]
                    const float* __restrict__ b_ih,
                    const float* __restrict__ b_hh) {
    __shared__ __align__(16) float As[2][BK][BM + APAD];  // stride 132
    __shared__ __align__(16) float Bs[2][BK][BN + APAD];

    const int tid = threadIdx.x;
    const int tx = tid & 15;          // col group 0..15
    const int ty = tid >> 4;          // row group 0..15
    const int m0 = blockIdx.x * BM;
    const int n0 = blockIdx.y * BN;

    // Loader mapping: each thread stages 8 floats of A and 8 of W (one row, 8 k's)
    const int lrow = tid >> 1;        // 0..127
    const int lkh  = (tid & 1) * 8;   // 0 or 8

    const float* aptr = A + (size_t)(m0 + lrow) * Isz;
    const float* wptr = W + (size_t)(n0 + lrow) * Isz;

    ull acc2[8][4];
#pragma unroll
    for (int i = 0; i < 8; ++i)
#pragma unroll
        for (int j = 0; j < 4; ++j) acc2[i][j] = 0ull;

    float4 ra0, ra1, rb0, rb1;

    // Preload tile 0
    ra0 = ldg_guard(aptr, lkh + 0);
    ra1 = ldg_guard(aptr, lkh + 4);
    rb0 = ldg_guard(wptr, lkh + 0);
    rb1 = ldg_guard(wptr, lkh + 4);
    {
        const float* f;
        f = (const float*)&ra0;
#pragma unroll
        for (int s = 0; s < 4; ++s) As[0][lkh + s][lrow] = f[s];
        f = (const float*)&ra1;
#pragma unroll
        for (int s = 0; s < 4; ++s) As[0][lkh + 4 + s][lrow] = f[s];
        f = (const float*)&rb0;
#pragma unroll
        for (int s = 0; s < 4; ++s) Bs[0][lkh + s][lrow] = f[s];
        f = (const float*)&rb1;
#pragma unroll
        for (int s = 0; s < 4; ++s) Bs[0][lkh + 4 + s][lrow] = f[s];
    }
    __syncthreads();

    int buf = 0;
    for (int tIdx = 0; tIdx < NTILES; ++tIdx) {
        const bool more = (tIdx + 1 < NTILES);
        if (more) {
            int k0 = (tIdx + 1) * BK;
            ra0 = ldg_guard(aptr, k0 + lkh + 0);
            ra1 = ldg_guard(aptr, k0 + lkh + 4);
            rb0 = ldg_guard(wptr, k0 + lkh + 0);
            rb1 = ldg_guard(wptr, k0 + lkh + 4);
        }

#pragma unroll
        for (int k = 0; k < BK; ++k) {
            float4 av0 = *(const float4*)&As[buf][k][ty * 8];
            float4 av1 = *(const float4*)&As[buf][k][ty * 8 + 4];
            longlong2 q0 = *(const longlong2*)&Bs[buf][k][tx * 8];
            longlong2 q1 = *(const longlong2*)&Bs[buf][k][tx * 8 + 4];
            ull bq[4];
            bq[0] = (ull)q0.x; bq[1] = (ull)q0.y;
            bq[2] = (ull)q1.x; bq[3] = (ull)q1.y;
            float av[8];
            av[0]=av0.x; av[1]=av0.y; av[2]=av0.z; av[3]=av0.w;
            av[4]=av1.x; av[5]=av1.y; av[6]=av1.z; av[7]=av1.w;
#pragma unroll
            for (int i = 0; i < 8; ++i) {
                ull a2 = pk2(av[i]);
#pragma unroll
                for (int j = 0; j < 4; ++j) ffma2(acc2[i][j], a2, bq[j]);
            }
        }

        if (more) {
            int nb = buf ^ 1;
            const float* f;
            f = (const float*)&ra0;
#pragma unroll
            for (int s = 0; s < 4; ++s) As[nb][lkh + s][lrow] = f[s];
            f = (const float*)&ra1;
#pragma unroll
            for (int s = 0; s < 4; ++s) As[nb][lkh + 4 + s][lrow] = f[s];
            f = (const float*)&rb0;
#pragma unroll
            for (int s = 0; s < 4; ++s) Bs[nb][lkh + s][lrow] = f[s];
            f = (const float*)&rb1;
#pragma unroll
            for (int s = 0; s < 4; ++s) Bs[nb][lkh + 4 + s][lrow] = f[s];
        }
        buf ^= 1;
        __syncthreads();
    }

    // Epilogue: add combined bias, write g_xg
    float bias[8];
#pragma unroll
    for (int j = 0; j < 8; ++j) bias[j] = b_ih[n0 + tx * 8 + j] + b_hh[n0 + tx * 8 + j];

#pragma unroll
    for (int i = 0; i < 8; ++i) {
        int m = m0 + ty * 8 + i;
        float2 p0 = upk(acc2[i][0]);
        float2 p1 = upk(acc2[i][1]);
        float2 p2 = upk(acc2[i][2]);
        float2 p3 = upk(acc2[i][3]);
        float4 v0, v1;
        v0.x = p0.x + bias[0]; v0.y = p0.y + bias[1];
        v0.z = p1.x + bias[2]; v0.w = p1.y + bias[3];
        v1.x = p2.x + bias[4]; v1.y = p2.y + bias[5];
        v1.z = p3.x + bias[6]; v1.w = p3.y + bias[7];
        float* dst = &g_xg[(size_t)m * G4 + n0 + tx * 8];
        *(float4*)dst = v0;
        *(float4*)(dst + 4) = v1;
    }
}

// ----------------------------------------------------------------------------
// Kernel 2: persistent recurrent LSTM + fused FC.
// Grid: 128 CTAs x 512 threads. CTA cb owns batch rows 2*cb, 2*cb+1.
// smem: W_hh rows 0..383 (i,f,g) padded stride 132; o-gate rows from L2.
// Thread j computes pre-activation gate j for both rows; threads 0..255 do
// the c/h update. Two barriers per step.
// ----------------------------------------------------------------------------
#define ROWS 2
#define WPAD 132

__global__ __launch_bounds__(512)
void lstm_fc_kernel(const float* __restrict__ W_hh,   // [512,128]
                    const float* __restrict__ fc_w,   // [1,128]
                    const float* __restrict__ fc_b,   // [1]
                    float* __restrict__ out) {        // [256]
    extern __shared__ __align__(16) float sm[];
    float* sW = sm;                    // 384 * 132
    float* sH = sm + 384 * WPAD;       // [2][128]
    float* sG = sH + ROWS * Hsz;       // [2][512]

    const int tid = threadIdx.x;       // 0..511
    const int b0 = blockIdx.x * ROWS;

    // Stage W_hh gates i,f,g into smem (padded rows, conflict-free LDS.128)
    for (int idx = tid; idx < 384 * Hsz; idx += 512)
        sW[(idx >> 7) * WPAD + (idx & 127)] = W_hh[idx];
    if (tid < ROWS * Hsz) sH[tid] = 0.f;

    const int r2 = tid >> 7;           // phase-2 row (valid for tid<256)
    const int n2 = tid & 127;
    float cst = 0.f;

    const float4* wg4 = (const float4*)(W_hh + (size_t)tid * Hsz); // tid>=384
    const float4* wp4 = (const float4*)(sW + tid * WPAD);          // tid<384
    const float* xp0 = g_xg + ((size_t)(b0 + 0) * Tsz) * G4 + tid;
    const float* xp1 = g_xg + ((size_t)(b0 + 1) * Tsz) * G4 + tid;

    __syncthreads();

    for (int t = 0; t < Tsz; ++t) {
        // Issue xg loads early; consumed only after the mat-vec
        float x0 = xp0[(size_t)t * G4];
        float x1 = xp1[(size_t)t * G4];

        float acc0 = 0.f, acc1 = 0.f;
        const float4* h0 = (const float4*)(sH);
        const float4* h1 = (const float4*)(sH + Hsz);

        if (tid < 384) {
#pragma unroll
            for (int k = 0; k < 32; ++k) {
                float4 w = wp4[k];
                float4 a = h0[k], b = h1[k];
                acc0 += w.x*a.x + w.y*a.y + w.z*a.z + w.w*a.w;
                acc1 += w.x*b.x + w.y*b.y + w.z*b.z + w.w*b.w;
            }
        } else {
#pragma unroll
            for (int k = 0; k < 32; ++k) {
                float4 w = wg4[k];
                float4 a = h0[k], b = h1[k];
                acc0 += w.x*a.x + w.y*a.y + w.z*a.z + w.w*a.w;
                acc1 += w.x*b.x + w.y*b.y + w.z*b.z + w.w*b.w;
            }
        }
        acc0 += x0; acc1 += x1;

        // j<256: sigmoid (i,f); 256..383: tanh (g); >=384: sigmoid (o)
        if (tid >= 256 && tid < 384) {
            acc0 = tanhf(acc0); acc1 = tanhf(acc1);
        } else {
            acc0 = sigmoidf_(acc0); acc1 = sigmoidf_(acc1);
        }
        sG[tid] = acc0;
        sG[G4 + tid] = acc1;
        __syncthreads();

        if (tid < 256) {
            float iv = sG[r2 * G4 + n2];
            float fv = sG[r2 * G4 + 128 + n2];
            float gv = sG[r2 * G4 + 256 + n2];
            float ov = sG[r2 * G4 + 384 + n2];
            cst = fv * cst + iv * gv;
            sH[r2 * Hsz + n2] = ov * tanhf(cst);
        }
        __syncthreads();
    }

    // Fused FC: out[b] = h_last[b] . fc_w + fc_b
    if (tid < ROWS) {
        float s = 0.f;
#pragma unroll 8
        for (int k = 0; k < Hsz; ++k) s += sH[tid * Hsz + k] * fc_w[k];
        out[b0 + tid] = s + fc_b[0];
    }
}

// ----------------------------------------------------------------------------
// Launch
// ----------------------------------------------------------------------------
extern "C" void kernel_launch(void* const* d_in, const int* in_sizes, int n_in,
                              void* d_out, int out_size) {
    const float* x    = (const float*)d_in[0];   // [256,512,300]
    const float* W_ih = (const float*)d_in[1];   // [512,300]
    const float* W_hh = (const float*)d_in[2];   // [512,128]
    const float* b_ih = (const float*)d_in[3];   // [512]
    const float* b_hh = (const float*)d_in[4];   // [512]
    const float* fc_w = (const float*)d_in[5];   // [1,128]
    const float* fc_b = (const float*)d_in[6];   // [1]
    float* out = (float*)d_out;                  // [256,1]

    // Kernel 1: input projection GEMM into g_xg
    dim3 grid1(Msz / BM, G4 / BN);  // (1024, 4)
    gemm_xg_kernel<<<grid1, 256>>>(x, W_ih, b_ih, b_hh);

    // Kernel 2: persistent recurrence + fused FC (128 CTAs)
    const int smem_bytes = (384 * WPAD + ROWS * Hsz + ROWS * G4) * sizeof(float); // 207872
    cudaFuncSetAttribute(lstm_fc_kernel,
                         cudaFuncAttributeMaxDynamicSharedMemorySize, smem_bytes);
    lstm_fc_kernel<<<Bsz / ROWS, 512, smem_bytes>>>(W_hh, fc_w, fc_b, out);
}

// round 3
// speedup vs baseline: 3.4041x; 2.9044x over previous
#include <cuda_runtime.h>
#include <cuda_fp16.h>
#include <math.h>

// Problem constants
#define Bsz   256
#define Tsz   512
#define Isz   300
#define Hsz   128
#define G4    512           // 4*H
#define Msz   (Bsz*Tsz)     // 131072

// Scratch for precomputed input gates: [B,T,4H] fp32 = 256 MiB
__device__ float g_xg[(size_t)Msz * G4];

typedef unsigned long long ull;
typedef unsigned int u32;

__device__ __forceinline__ float sigmoid_fast(float x) {
    return 0.5f * __tanhf(0.5f * x) + 0.5f;
}

// Packed fp32x2 helpers (GEMM)
__device__ __forceinline__ ull pk2(float x) {
    ull r; asm("mov.b64 %0, {%1, %1};" : "=l"(r) : "f"(x)); return r;
}
__device__ __forceinline__ void ffma2(ull& d, ull a, ull b) {
    asm("fma.rn.f32x2 %0, %1, %2, %0;" : "+l"(d) : "l"(a), "l"(b));
}
__device__ __forceinline__ float2 upk(ull v) {
    float2 r; asm("mov.b64 {%0, %1}, %2;" : "=f"(r.x), "=f"(r.y) : "l"(v)); return r;
}

// ----------------------------------------------------------------------------
// Kernel 1: xg = x @ W_ih^T + (b_ih + b_hh)   (unchanged from round 2)
// ----------------------------------------------------------------------------
#define BM 128
#define BN 128
#define BK 16
#define NTILES 19
#define APAD 4

__device__ __forceinline__ float4 ldg_guard(const float* __restrict__ p, int col) {
    if (col < Isz) return *(const float4*)(p + col);
    return make_float4(0.f, 0.f, 0.f, 0.f);
}

__global__ __launch_bounds__(256, 2)
void gemm_xg_kernel(const float* __restrict__ A,
                    const float* __restrict__ W,
                    const float* __restrict__ b_ih,
                    const float* __restrict__ b_hh) {
    __shared__ __align__(16) float As[2][BK][BM + APAD];
    __shared__ __align__(16) float Bs[2][BK][BN + APAD];

    const int tid = threadIdx.x;
    const int tx = tid & 15;
    const int ty = tid >> 4;
    const int m0 = blockIdx.x * BM;
    const int n0 = blockIdx.y * BN;

    const int lrow = tid >> 1;
    const int lkh  = (tid & 1) * 8;

    const float* aptr = A + (size_t)(m0 + lrow) * Isz;
    const float* wptr = W + (size_t)(n0 + lrow) * Isz;

    ull acc2[8][4];
#pragma unroll
    for (int i = 0; i < 8; ++i)
#pragma unroll
        for (int j = 0; j < 4; ++j) acc2[i][j] = 0ull;

    float4 ra0, ra1, rb0, rb1;
    ra0 = ldg_guard(aptr, lkh + 0);
    ra1 = ldg_guard(aptr, lkh + 4);
    rb0 = ldg_guard(wptr, lkh + 0);
    rb1 = ldg_guard(wptr, lkh + 4);
    {
        const float* f;
        f = (const float*)&ra0;
#pragma unroll
        for (int s = 0; s < 4; ++s) As[0][lkh + s][lrow] = f[s];
        f = (const float*)&ra1;
#pragma unroll
        for (int s = 0; s < 4; ++s) As[0][lkh + 4 + s][lrow] = f[s];
        f = (const float*)&rb0;
#pragma unroll
        for (int s = 0; s < 4; ++s) Bs[0][lkh + s][lrow] = f[s];
        f = (const float*)&rb1;
#pragma unroll
        for (int s = 0; s < 4; ++s) Bs[0][lkh + 4 + s][lrow] = f[s];
    }
    __syncthreads();

    int buf = 0;
    for (int tIdx = 0; tIdx < NTILES; ++tIdx) {
        const bool more = (tIdx + 1 < NTILES);
        if (more) {
            int k0 = (tIdx + 1) * BK;
            ra0 = ldg_guard(aptr, k0 + lkh + 0);
            ra1 = ldg_guard(aptr, k0 + lkh + 4);
            rb0 = ldg_guard(wptr, k0 + lkh + 0);
            rb1 = ldg_guard(wptr, k0 + lkh + 4);
        }

#pragma unroll
        for (int k = 0; k < BK; ++k) {
            float4 av0 = *(const float4*)&As[buf][k][ty * 8];
            float4 av1 = *(const float4*)&As[buf][k][ty * 8 + 4];
            longlong2 q0 = *(const longlong2*)&Bs[buf][k][tx * 8];
            longlong2 q1 = *(const longlong2*)&Bs[buf][k][tx * 8 + 4];
            ull bq[4];
            bq[0] = (ull)q0.x; bq[1] = (ull)q0.y;
            bq[2] = (ull)q1.x; bq[3] = (ull)q1.y;
            float av[8];
            av[0]=av0.x; av[1]=av0.y; av[2]=av0.z; av[3]=av0.w;
            av[4]=av1.x; av[5]=av1.y; av[6]=av1.z; av[7]=av1.w;
#pragma unroll
            for (int i = 0; i < 8; ++i) {
                ull a2 = pk2(av[i]);
#pragma unroll
                for (int j = 0; j < 4; ++j) ffma2(acc2[i][j], a2, bq[j]);
            }
        }

        if (more) {
            int nb = buf ^ 1;
            const float* f;
            f = (const float*)&ra0;
#pragma unroll
            for (int s = 0; s < 4; ++s) As[nb][lkh + s][lrow] = f[s];
            f = (const float*)&ra1;
#pragma unroll
            for (int s = 0; s < 4; ++s) As[nb][lkh + 4 + s][lrow] = f[s];
            f = (const float*)&rb0;
#pragma unroll
            for (int s = 0; s < 4; ++s) Bs[nb][lkh + s][lrow] = f[s];
            f = (const float*)&rb1;
#pragma unroll
            for (int s = 0; s < 4; ++s) Bs[nb][lkh + 4 + s][lrow] = f[s];
        }
        buf ^= 1;
        __syncthreads();
    }

    float bias[8];
#pragma unroll
    for (int j = 0; j < 8; ++j) bias[j] = b_ih[n0 + tx * 8 + j] + b_hh[n0 + tx * 8 + j];

#pragma unroll
    for (int i = 0; i < 8; ++i) {
        int m = m0 + ty * 8 + i;
        float2 p0 = upk(acc2[i][0]);
        float2 p1 = upk(acc2[i][1]);
        float2 p2 = upk(acc2[i][2]);
        float2 p3 = upk(acc2[i][3]);
        float4 v0, v1;
        v0.x = p0.x + bias[0]; v0.y = p0.y + bias[1];
        v0.z = p1.x + bias[2]; v0.w = p1.y + bias[3];
        v1.x = p2.x + bias[4]; v1.y = p2.y + bias[5];
        v1.z = p3.x + bias[6]; v1.w = p3.y + bias[7];
        float* dst = &g_xg[(size_t)m * G4 + n0 + tx * 8];
        *(float4*)dst = v0;
        *(float4*)(dst + 4) = v1;
    }
}

// ----------------------------------------------------------------------------
// Kernel 2: recurrence with register-resident fp16 W_hh via mma.sync m16n8k16.
// Grid: 128 CTAs x 512 threads (16 warps). CTA owns 2 batch rows (mma N dim,
// cols 0..1 real, 2..7 zero-padded).
// Warp w owns gate rows [32w, 32w+32): A-fragments (fp16) held in registers,
// loaded ONCE. Per step: B frag (fp16 h) from 2KB smem, 16 HMMA, activations,
// cross-warp gate exchange through smem, c/h update, h written back in
// B-fragment layout. No W_hh traffic in the loop at all.
// ----------------------------------------------------------------------------
#define ROWS 2

__device__ __forceinline__ void mma16816(float& c0, float& c1, float& c2, float& c3,
                                         u32 a0, u32 a1, u32 a2, u32 a3,
                                         u32 b0, u32 b1) {
    asm volatile(
        "mma.sync.aligned.m16n8k16.row.col.f32.f16.f16.f32 "
        "{%0,%1,%2,%3}, {%4,%5,%6,%7}, {%8,%9}, {%0,%1,%2,%3};"
        : "+f"(c0), "+f"(c1), "+f"(c2), "+f"(c3)
        : "r"(a0), "r"(a1), "r"(a2), "r"(a3), "r"(b0), "r"(b1));
}

__device__ __forceinline__ u32 packh2(float lo, float hi) {
    __half2 h = __floats2half2_rn(lo, hi);
    return *(u32*)&h;
}

__global__ __launch_bounds__(512, 1)
void lstm_fc_kernel(const float* __restrict__ W_hh,   // [512,128]
                    const float* __restrict__ fc_w,   // [1,128]
                    const float* __restrict__ fc_b,   // [1]
                    float* __restrict__ out) {        // [256]
    // smem
    __shared__ __align__(16) ull  sFrag[8 * 32];        // B fragments: [kc][lane], 2KB
    __shared__ float sG[ROWS * G4];                     // gate exchange, 4KB
    __shared__ float sH[ROWS * Hsz];                    // fp32 h for final FC
    __shared__ float sXG[2][ROWS * G4];                 // xg double buffer, 8KB

    const int tid  = threadIdx.x;
    const int wid  = tid >> 5;
    const int lane = tid & 31;
    const int b0   = blockIdx.x * ROWS;
    const int wbase = wid * 32;                         // gate-row base of this warp

    // ---- Load W_hh fragments into registers (once) ----
    // wa[kc][mt][r]: A frag regs for mma (16x16 fp16 tile each)
    u32 wa[8][2][4];
    {
        const int mrow = lane >> 2;          // 0..7
        const int kcol = (lane & 3) * 2;     // 0,2,4,6
#pragma unroll
        for (int kc = 0; kc < 8; ++kc) {
#pragma unroll
            for (int mt = 0; mt < 2; ++mt) {
                int r0 = wbase + mt * 16 + mrow;
                int k0 = kc * 16 + kcol;
                float2 w00 = *(const float2*)(W_hh + (size_t)r0 * Hsz + k0);
                float2 w10 = *(const float2*)(W_hh + (size_t)(r0 + 8) * Hsz + k0);
                float2 w01 = *(const float2*)(W_hh + (size_t)r0 * Hsz + k0 + 8);
                float2 w11 = *(const float2*)(W_hh + (size_t)(r0 + 8) * Hsz + k0 + 8);
                wa[kc][mt][0] = packh2(w00.x, w00.y);
                wa[kc][mt][1] = packh2(w10.x, w10.y);
                wa[kc][mt][2] = packh2(w01.x, w01.y);
                wa[kc][mt][3] = packh2(w11.x, w11.y);
            }
        }
    }

    // ---- Init shared state ----
    if (tid < 256) sFrag[tid] = 0ull;                  // h0 = 0 (all 8 N cols)
    if (tid < ROWS * Hsz) sH[tid] = 0.f;
    // preload xg for t=0
    {
        int r = tid >> 8;                  // 0..1
        int off = (tid & 255) * 2;
        float2 v = *(const float2*)(g_xg + (((size_t)(b0 + r)) * Tsz + 0) * G4 + off);
        sXG[0][r * G4 + off]     = v.x;
        sXG[0][r * G4 + off + 1] = v.y;
    }

    // c-state: phase-2 threads (tid<256) own c for (r = tid>>7, n = tid&127)
    float cst = 0.f;
    const int r2 = tid >> 7;
    const int n2 = tid & 127;

    const bool act_lane = ((lane & 3) == 0);
    const int mrow_act = lane >> 2;        // 0..7 (valid on act lanes)
    const int gate = wid >> 2;             // 0:i 1:f 2:g 3:o (uniform per warp)

    __syncthreads();

    int buf = 0;
    for (int t = 0; t < Tsz; ++t) {
        // ---- MMA: gates_pre = W_hh @ h ----
        float c0[4] = {0.f, 0.f, 0.f, 0.f};
        float c1[4] = {0.f, 0.f, 0.f, 0.f};
#pragma unroll
        for (int kc = 0; kc < 8; ++kc) {
            ull bv = sFrag[kc * 32 + lane];
            u32 b0r = (u32)bv;
            u32 b1r = (u32)(bv >> 32);
            mma16816(c0[0], c0[1], c0[2], c0[3],
                     wa[kc][0][0], wa[kc][0][1], wa[kc][0][2], wa[kc][0][3], b0r, b1r);
            mma16816(c1[0], c1[1], c1[2], c1[3],
                     wa[kc][1][0], wa[kc][1][1], wa[kc][1][2], wa[kc][1][3], b0r, b1r);
        }

        // ---- Prefetch xg for t+1 (issue LDG early) ----
        float2 xnext = make_float2(0.f, 0.f);
        int roff, coff;
        {
            roff = tid >> 8;
            coff = (tid & 255) * 2;
            if (t + 1 < Tsz)
                xnext = *(const float2*)(g_xg + (((size_t)(b0 + roff)) * Tsz + (t + 1)) * G4 + coff);
        }

        // ---- Activations (act lanes only; cols 0,1 = real batch rows) ----
        if (act_lane) {
#pragma unroll
            for (int mt = 0; mt < 2; ++mt) {
                float* cc = (mt == 0) ? c0 : c1;
                int mlow = wbase + mt * 16 + mrow_act;
                float v00 = cc[0] + sXG[buf][mlow];              // r=0, m=mlow
                float v01 = cc[1] + sXG[buf][G4 + mlow];         // r=1, m=mlow
                float v10 = cc[2] + sXG[buf][mlow + 8];          // r=0, m=mlow+8
                float v11 = cc[3] + sXG[buf][G4 + mlow + 8];     // r=1, m=mlow+8
                if (gate == 2) {
                    v00 = __tanhf(v00); v01 = __tanhf(v01);
                    v10 = __tanhf(v10); v11 = __tanhf(v11);
                } else {
                    v00 = sigmoid_fast(v00); v01 = sigmoid_fast(v01);
                    v10 = sigmoid_fast(v10); v11 = sigmoid_fast(v11);
                }
                sG[mlow]           = v00;
                sG[G4 + mlow]      = v01;
                sG[mlow + 8]       = v10;
                sG[G4 + mlow + 8]  = v11;
            }
        }

        // stage next xg into the other buffer
        sXG[buf ^ 1][roff * G4 + coff]     = xnext.x;
        sXG[buf ^ 1][roff * G4 + coff + 1] = xnext.y;

        __syncthreads();

        // ---- c/h update (threads 0..255), write h back as fp16 B-fragment ----
        if (tid < 256) {
            float iv = sG[r2 * G4 + n2];
            float fv = sG[r2 * G4 + 128 + n2];
            float gv = sG[r2 * G4 + 256 + n2];
            float ov = sG[r2 * G4 + 384 + n2];
            cst = fv * cst + iv * gv;
            float h = ov * __tanhf(cst);
            sH[r2 * Hsz + n2] = h;
            // B-frag position of h[r2][n2]:
            int kc   = n2 >> 4;
            int kw   = n2 & 15;
            int reg  = (kw >> 3) & 1;
            int ln   = 4 * r2 + ((kw & 7) >> 1);
            __half* fr = (__half*)&sFrag[kc * 32 + ln];
            fr[reg * 2 + (kw & 1)] = __float2half_rn(h);
        }
        __syncthreads();
        buf ^= 1;
    }

    // ---- Fused FC ----
    if (tid < ROWS) {
        float s = 0.f;
#pragma unroll 8
        for (int k = 0; k < Hsz; ++k) s += sH[tid * Hsz + k] * fc_w[k];
        out[b0 + tid] = s + fc_b[0];
    }
}

// ----------------------------------------------------------------------------
// Launch
// ----------------------------------------------------------------------------
extern "C" void kernel_launch(void* const* d_in, const int* in_sizes, int n_in,
                              void* d_out, int out_size) {
    const float* x    = (const float*)d_in[0];
    const float* W_ih = (const float*)d_in[1];
    const float* W_hh = (const float*)d_in[2];
    const float* b_ih = (const float*)d_in[3];
    const float* b_hh = (const float*)d_in[4];
    const float* fc_w = (const float*)d_in[5];
    const float* fc_b = (const float*)d_in[6];
    float* out = (float*)d_out;

    dim3 grid1(Msz / BM, G4 / BN);  // (1024, 4)
    gemm_xg_kernel<<<grid1, 256>>>(x, W_ih, b_ih, b_hh);

    lstm_fc_kernel<<<Bsz / ROWS, 512>>>(W_hh, fc_w, fc_b, out);
}

// round 6
// speedup vs baseline: 3.5823x; 1.0524x over previous
#include <cuda_runtime.h>
#include <cuda_fp16.h>
#include <math.h>

// Problem constants
#define Bsz   256
#define Tsz   512
#define Isz   300
#define Hsz   128
#define G4    512           // 4*H
#define Msz   (Bsz*Tsz)     // 131072
#define KP    320           // padded K for x (multiple of 16)

// Scratch: precomputed input gates [B,T,4H] fp32 (256 MiB)
__device__ float g_xg[(size_t)Msz * G4];
// Scratch: x split into fp16 hi/lo, padded to KP (80 MiB each)
__device__ __half g_xhi[(size_t)Msz * KP];
__device__ __half g_xlo[(size_t)Msz * KP];

typedef unsigned long long ull;
typedef unsigned int u32;

__device__ __forceinline__ float sigmoid_fast(float x) {
    return 0.5f * __tanhf(0.5f * x) + 0.5f;
}

__device__ __forceinline__ void mma16816(float& c0, float& c1, float& c2, float& c3,
                                         u32 a0, u32 a1, u32 a2, u32 a3,
                                         u32 b0, u32 b1) {
    asm volatile(
        "mma.sync.aligned.m16n8k16.row.col.f32.f16.f16.f32 "
        "{%0,%1,%2,%3}, {%4,%5,%6,%7}, {%8,%9}, {%0,%1,%2,%3};"
        : "+f"(c0), "+f"(c1), "+f"(c2), "+f"(c3)
        : "r"(a0), "r"(a1), "r"(a2), "r"(a3), "r"(b0), "r"(b1));
}

__device__ __forceinline__ u32 packh2(float lo, float hi) {
    __half2 h = __floats2half2_rn(lo, hi);
    return *(u32*)&h;
}

// ----------------------------------------------------------------------------
// Kernel 0: split x into fp16 hi/lo, zero-padded to KP columns.
// ----------------------------------------------------------------------------
__global__ __launch_bounds__(256)
void convert_x(const float* __restrict__ x) {
    size_t idx = (size_t)blockIdx.x * 256 + threadIdx.x;
    if (idx >= (size_t)Msz * KP) return;
    int k = (int)(idx % KP);
    size_t m = idx / KP;
    float v = (k < Isz) ? x[m * Isz + k] : 0.f;
    __half h = __float2half_rn(v);
    g_xhi[idx] = h;
    g_xlo[idx] = __float2half_rn(v - __half2float(h));
}

// ----------------------------------------------------------------------------
// Kernel 1: xg = x @ W_ih^T + (b_ih+b_hh), fp16 split MMA (3 passes ~ fp32).
// Grid (4, 256), 256 threads = 8 warps (4m x 2n); CTA tile 128m x 128n,
// it-loop over 4 m-tiles. W slice hi/lo resident in smem; A fragments loaded
// per-lane from global fp16 (proven LSTM fragment layout, no ldmatrix), B
// fragments per-lane from smem. No barriers in the k-loop.
// ----------------------------------------------------------------------------
#define WSTR  328                  // halves; 656B = 41*16B (conflict-free)
#define WHALF (128*WSTR)
#define SMEM_GEMM (2*WHALF*2)      // 167936 bytes

__global__ __launch_bounds__(256, 1)
void gemm_xg_tc2(const float* __restrict__ W,    // W_ih [512,300]
                 const float* __restrict__ b_ih,
                 const float* __restrict__ b_hh) {
    extern __shared__ __align__(16) __half sh[];
    __half* sWhi = sh;             // [128][WSTR]
    __half* sWlo = sh + WHALF;

    const int tid  = threadIdx.x;
    const int wid  = tid >> 5;
    const int lane = tid & 31;
    const int wm   = wid & 3;      // 0..3  (m sub-tile)
    const int wn   = wid >> 2;     // 0..1  (n sub-tile)
    const int n0   = blockIdx.x * 128;

    const int fr = lane >> 2;      // fragment row/col-group 0..7
    const int fc = (lane & 3) * 2; // fragment k/col offset (even)

    // ---- Stage W slice hi/lo (once per CTA) ----
    for (int idx = tid; idx < 128 * KP; idx += 256) {
        int r = idx / KP, k = idx - r * KP;
        float v = (k < Isz) ? W[(size_t)(n0 + r) * Isz + k] : 0.f;
        __half h = __float2half_rn(v);
        sWhi[r * WSTR + k] = h;
        sWlo[r * WSTR + k] = __float2half_rn(v - __half2float(h));
    }
    __syncthreads();

    // ---- Bias (depends only on n) ----
    float bi0[8], bi1[8];
#pragma unroll
    for (int nt = 0; nt < 8; ++nt) {
        int n = n0 + wn * 64 + nt * 8 + fc;
        bi0[nt] = b_ih[n] + b_hh[n];
        bi1[nt] = b_ih[n + 1] + b_hh[n + 1];
    }

    for (int it = 0; it < 4; ++it) {
        const int m0 = (blockIdx.y + 256 * it) * 128;
        const int mb = m0 + wm * 32;

        float acc[2][8][4];
#pragma unroll
        for (int mt = 0; mt < 2; ++mt)
#pragma unroll
            for (int nt = 0; nt < 8; ++nt)
#pragma unroll
                for (int q = 0; q < 4; ++q) acc[mt][nt][q] = 0.f;

        // A fragment double buffer: [buf][mt][reg]
        u32 Ah[2][2][4], Al[2][2][4];

        // proven layout: a0=(row fr, k fc), a1=row+8, a2=k+8, a3=row+8,k+8
#define LOADA(BUF, K0)                                                        \
        {                                                                     \
            _Pragma("unroll")                                                 \
            for (int mt = 0; mt < 2; ++mt) {                                  \
                size_t base = (size_t)(mb + mt * 16 + fr) * KP + (K0) + fc;   \
                Ah[BUF][mt][0] = *(const u32*)(g_xhi + base);                 \
                Ah[BUF][mt][1] = *(const u32*)(g_xhi + base + 8 * KP);        \
                Ah[BUF][mt][2] = *(const u32*)(g_xhi + base + 8);             \
                Ah[BUF][mt][3] = *(const u32*)(g_xhi + base + 8 * KP + 8);    \
                Al[BUF][mt][0] = *(const u32*)(g_xlo + base);                 \
                Al[BUF][mt][1] = *(const u32*)(g_xlo + base + 8 * KP);        \
                Al[BUF][mt][2] = *(const u32*)(g_xlo + base + 8);             \
                Al[BUF][mt][3] = *(const u32*)(g_xlo + base + 8 * KP + 8);    \
            }                                                                 \
        }

        LOADA(0, 0)

        for (int kk = 0; kk < 20; ++kk) {
            const int cur = kk & 1;
            const int nxt = cur ^ 1;
            if (kk < 19) LOADA(nxt, (kk + 1) * 16)

            const int k0 = kk * 16;
            const __half* bbase = sWhi + (wn * 64 + fr) * WSTR + k0 + fc;
#pragma unroll
            for (int nt = 0; nt < 8; ++nt) {
                const __half* bph = bbase + nt * 8 * WSTR;
                u32 bh0 = *(const u32*)bph;
                u32 bh1 = *(const u32*)(bph + 8);
                u32 bl0 = *(const u32*)(bph + WHALF);
                u32 bl1 = *(const u32*)(bph + WHALF + 8);
                // hi*hi
                mma16816(acc[0][nt][0], acc[0][nt][1], acc[0][nt][2], acc[0][nt][3],
                         Ah[cur][0][0], Ah[cur][0][1], Ah[cur][0][2], Ah[cur][0][3], bh0, bh1);
                mma16816(acc[1][nt][0], acc[1][nt][1], acc[1][nt][2], acc[1][nt][3],
                         Ah[cur][1][0], Ah[cur][1][1], Ah[cur][1][2], Ah[cur][1][3], bh0, bh1);
                // lo*hi
                mma16816(acc[0][nt][0], acc[0][nt][1], acc[0][nt][2], acc[0][nt][3],
                         Al[cur][0][0], Al[cur][0][1], Al[cur][0][2], Al[cur][0][3], bh0, bh1);
                mma16816(acc[1][nt][0], acc[1][nt][1], acc[1][nt][2], acc[1][nt][3],
                         Al[cur][1][0], Al[cur][1][1], Al[cur][1][2], Al[cur][1][3], bh0, bh1);
                // hi*lo
                mma16816(acc[0][nt][0], acc[0][nt][1], acc[0][nt][2], acc[0][nt][3],
                         Ah[cur][0][0], Ah[cur][0][1], Ah[cur][0][2], Ah[cur][0][3], bl0, bl1);
                mma16816(acc[1][nt][0], acc[1][nt][1], acc[1][nt][2], acc[1][nt][3],
                         Ah[cur][1][0], Ah[cur][1][1], Ah[cur][1][2], Ah[cur][1][3], bl0, bl1);
            }
        }
#undef LOADA

        // ---- Epilogue (proven accumulator mapping) ----
#pragma unroll
        for (int mt = 0; mt < 2; ++mt) {
            int m = mb + mt * 16 + fr;
            float* dst0 = g_xg + (size_t)m * G4 + n0 + wn * 64;
            float* dst1 = dst0 + (size_t)8 * G4;    // row m+8
#pragma unroll
            for (int nt = 0; nt < 8; ++nt) {
                float2 v0 = make_float2(acc[mt][nt][0] + bi0[nt], acc[mt][nt][1] + bi1[nt]);
                float2 v1 = make_float2(acc[mt][nt][2] + bi0[nt], acc[mt][nt][3] + bi1[nt]);
                *(float2*)(dst0 + nt * 8 + fc) = v0;
                *(float2*)(dst1 + nt * 8 + fc) = v1;
            }
        }
    }
}

// ----------------------------------------------------------------------------
// Kernel 2: recurrence with register-resident fp16 W_hh via mma.sync m16n8k16.
// (unchanged — proven at rel_err 3.6e-5)
// ----------------------------------------------------------------------------
#define ROWS 2

__global__ __launch_bounds__(512, 1)
void lstm_fc_kernel(const float* __restrict__ W_hh,   // [512,128]
                    const float* __restrict__ fc_w,   // [1,128]
                    const float* __restrict__ fc_b,   // [1]
                    float* __restrict__ out) {        // [256]
    __shared__ __align__(16) ull  sFrag[8 * 32];
    __shared__ float sG[ROWS * G4];
    __shared__ float sH[ROWS * Hsz];
    __shared__ float sXG[2][ROWS * G4];

    const int tid  = threadIdx.x;
    const int wid  = tid >> 5;
    const int lane = tid & 31;
    const int b0   = blockIdx.x * ROWS;
    const int wbase = wid * 32;

    u32 wa[8][2][4];
    {
        const int mrow = lane >> 2;
        const int kcol = (lane & 3) * 2;
#pragma unroll
        for (int kc = 0; kc < 8; ++kc) {
#pragma unroll
            for (int mt = 0; mt < 2; ++mt) {
                int r0 = wbase + mt * 16 + mrow;
                int k0 = kc * 16 + kcol;
                float2 w00 = *(const float2*)(W_hh + (size_t)r0 * Hsz + k0);
                float2 w10 = *(const float2*)(W_hh + (size_t)(r0 + 8) * Hsz + k0);
                float2 w01 = *(const float2*)(W_hh + (size_t)r0 * Hsz + k0 + 8);
                float2 w11 = *(const float2*)(W_hh + (size_t)(r0 + 8) * Hsz + k0 + 8);
                wa[kc][mt][0] = packh2(w00.x, w00.y);
                wa[kc][mt][1] = packh2(w10.x, w10.y);
                wa[kc][mt][2] = packh2(w01.x, w01.y);
                wa[kc][mt][3] = packh2(w11.x, w11.y);
            }
        }
    }

    if (tid < 256) sFrag[tid] = 0ull;
    if (tid < ROWS * Hsz) sH[tid] = 0.f;
    {
        int r = tid >> 8;
        int off = (tid & 255) * 2;
        float2 v = *(const float2*)(g_xg + (((size_t)(b0 + r)) * Tsz + 0) * G4 + off);
        sXG[0][r * G4 + off]     = v.x;
        sXG[0][r * G4 + off + 1] = v.y;
    }

    float cst = 0.f;
    const int r2 = tid >> 7;
    const int n2 = tid & 127;

    const bool act_lane = ((lane & 3) == 0);
    const int mrow_act = lane >> 2;
    const int gate = wid >> 2;

    __syncthreads();

    int buf = 0;
    for (int t = 0; t < Tsz; ++t) {
        float c0[4] = {0.f, 0.f, 0.f, 0.f};
        float c1[4] = {0.f, 0.f, 0.f, 0.f};
#pragma unroll
        for (int kc = 0; kc < 8; ++kc) {
            ull bv = sFrag[kc * 32 + lane];
            u32 b0r = (u32)bv;
            u32 b1r = (u32)(bv >> 32);
            mma16816(c0[0], c0[1], c0[2], c0[3],
                     wa[kc][0][0], wa[kc][0][1], wa[kc][0][2], wa[kc][0][3], b0r, b1r);
            mma16816(c1[0], c1[1], c1[2], c1[3],
                     wa[kc][1][0], wa[kc][1][1], wa[kc][1][2], wa[kc][1][3], b0r, b1r);
        }

        float2 xnext = make_float2(0.f, 0.f);
        int roff, coff;
        {
            roff = tid >> 8;
            coff = (tid & 255) * 2;
            if (t + 1 < Tsz)
                xnext = *(const float2*)(g_xg + (((size_t)(b0 + roff)) * Tsz + (t + 1)) * G4 + coff);
        }

        if (act_lane) {
#pragma unroll
            for (int mt = 0; mt < 2; ++mt) {
                float* cc = (mt == 0) ? c0 : c1;
                int mlow = wbase + mt * 16 + mrow_act;
                float v00 = cc[0] + sXG[buf][mlow];
                float v01 = cc[1] + sXG[buf][G4 + mlow];
                float v10 = cc[2] + sXG[buf][mlow + 8];
                float v11 = cc[3] + sXG[buf][G4 + mlow + 8];
                if (gate == 2) {
                    v00 = __tanhf(v00); v01 = __tanhf(v01);
                    v10 = __tanhf(v10); v11 = __tanhf(v11);
                } else {
                    v00 = sigmoid_fast(v00); v01 = sigmoid_fast(v01);
                    v10 = sigmoid_fast(v10); v11 = sigmoid_fast(v11);
                }
                sG[mlow]           = v00;
                sG[G4 + mlow]      = v01;
                sG[mlow + 8]       = v10;
                sG[G4 + mlow + 8]  = v11;
            }
        }

        sXG[buf ^ 1][roff * G4 + coff]     = xnext.x;
        sXG[buf ^ 1][roff * G4 + coff + 1] = xnext.y;

        __syncthreads();

        if (tid < 256) {
            float iv = sG[r2 * G4 + n2];
            float fv = sG[r2 * G4 + 128 + n2];
            float gv = sG[r2 * G4 + 256 + n2];
            float ov = sG[r2 * G4 + 384 + n2];
            cst = fv * cst + iv * gv;
            float h = ov * __tanhf(cst);
            sH[r2 * Hsz + n2] = h;
            int kc   = n2 >> 4;
            int kw   = n2 & 15;
            int reg  = (kw >> 3) & 1;
            int ln   = 4 * r2 + ((kw & 7) >> 1);
            __half* fr = (__half*)&sFrag[kc * 32 + ln];
            fr[reg * 2 + (kw & 1)] = __float2half_rn(h);
        }
        __syncthreads();
        buf ^= 1;
    }

    if (tid < ROWS) {
        float s = 0.f;
#pragma unroll 8
        for (int k = 0; k < Hsz; ++k) s += sH[tid * Hsz + k] * fc_w[k];
        out[b0 + tid] = s + fc_b[0];
    }
}

// ----------------------------------------------------------------------------
// Launch
// ----------------------------------------------------------------------------
extern "C" void kernel_launch(void* const* d_in, const int* in_sizes, int n_in,
                              void* d_out, int out_size) {
    const float* x    = (const float*)d_in[0];
    const float* W_ih = (const float*)d_in[1];
    const float* W_hh = (const float*)d_in[2];
    const float* b_ih = (const float*)d_in[3];
    const float* b_hh = (const float*)d_in[4];
    const float* fc_w = (const float*)d_in[5];
    const float* fc_b = (const float*)d_in[6];
    float* out = (float*)d_out;

    // Kernel 0: x -> fp16 hi/lo (padded)
    size_t total = (size_t)Msz * KP;
    convert_x<<<(unsigned)((total + 255) / 256), 256>>>(x);

    // Kernel 1: tensor-core split GEMM
    cudaFuncSetAttribute(gemm_xg_tc2,
                         cudaFuncAttributeMaxDynamicSharedMemorySize, SMEM_GEMM);
    gemm_xg_tc2<<<dim3(4, 256), 256, SMEM_GEMM>>>(W_ih, b_ih, b_hh);

    // Kernel 2: persistent recurrence + fused FC
    lstm_fc_kernel<<<Bsz / ROWS, 512>>>(W_hh, fc_w, fc_b, out);
}

// round 8
// speedup vs baseline: 3.8659x; 1.0792x over previous
#include <cuda_runtime.h>
#include <cuda_fp16.h>
#include <math.h>

// Problem constants
#define Bsz   256
#define Tsz   512
#define Isz   300
#define Hsz   128
#define G4    512           // 4*H
#define Msz   (Bsz*Tsz)     // 131072
#define KP    320           // padded K for x (multiple of 16)

// Scratch: precomputed input gates [B,T,4H] fp32 (256 MiB)
__device__ float g_xg[(size_t)Msz * G4];
// Scratch: x split into fp16 hi/lo, padded to KP (80 MiB each)
__device__ __half g_xhi[(size_t)Msz * KP];
__device__ __half g_xlo[(size_t)Msz * KP];

typedef unsigned long long ull;
typedef unsigned int u32;

__device__ __forceinline__ float sigmoid_fast(float x) {
    return 0.5f * __tanhf(0.5f * x) + 0.5f;
}

__device__ __forceinline__ void mma16816(float& c0, float& c1, float& c2, float& c3,
                                         u32 a0, u32 a1, u32 a2, u32 a3,
                                         u32 b0, u32 b1) {
    asm volatile(
        "mma.sync.aligned.m16n8k16.row.col.f32.f16.f16.f32 "
        "{%0,%1,%2,%3}, {%4,%5,%6,%7}, {%8,%9}, {%0,%1,%2,%3};"
        : "+f"(c0), "+f"(c1), "+f"(c2), "+f"(c3)
        : "r"(a0), "r"(a1), "r"(a2), "r"(a3), "r"(b0), "r"(b1));
}

__device__ __forceinline__ u32 packh2(float lo, float hi) {
    __half2 h = __floats2half2_rn(lo, hi);
    return *(u32*)&h;
}

// ----------------------------------------------------------------------------
// Kernel 0: split x into fp16 hi/lo, padded to KP. One thread per 8 columns,
// 16B vector stores.
// ----------------------------------------------------------------------------
#define CVT_TPR (KP / 8)   // 40 threads per row
__global__ __launch_bounds__(256)
void convert_x(const float* __restrict__ x) {
    size_t g = (size_t)blockIdx.x * 256 + threadIdx.x;
    if (g >= (size_t)Msz * CVT_TPR) return;
    size_t m = g / CVT_TPR;
    int k0 = (int)(g % CVT_TPR) * 8;

    const float* xr = x + m * Isz;
    __half hv[8], lv[8];
#pragma unroll
    for (int i = 0; i < 8; ++i) {
        int k = k0 + i;
        float v = (k < Isz) ? __ldg(xr + k) : 0.f;
        __half h = __float2half_rn(v);
        hv[i] = h;
        lv[i] = __float2half_rn(v - __half2float(h));
    }
    size_t off = m * KP + k0;
    *(uint4*)(g_xhi + off) = *(const uint4*)hv;
    *(uint4*)(g_xlo + off) = *(const uint4*)lv;
}

// ----------------------------------------------------------------------------
// Kernel 1: xg = x @ W_ih^T + (b_ih+b_hh), fp16 split MMA, 2 passes:
//   x_hi*W_hi + x_lo*W_hi  (W_lo dropped; ~2.8e-4 pre-act error, damped)
// Grid (4, 256), 512 threads = 16 warps (4m x 4n); CTA tile 128m x 128n,
// it-loop over 4 m-tiles. W_hi slice resident in smem (84KB); A fragments
// per-lane from global fp16 (double-buffered); no barriers in k-loop.
// ----------------------------------------------------------------------------
#define WSTR  328                  // halves; 656B = 41*16B (conflict-free)
#define WHALF (128*WSTR)
#define SMEM_GEMM (WHALF*2)        // 83968 bytes (W_hi only)

__global__ __launch_bounds__(512, 1)
void gemm_xg_tc2(const float* __restrict__ W,    // W_ih [512,300]
                 const float* __restrict__ b_ih,
                 const float* __restrict__ b_hh) {
    extern __shared__ __align__(16) __half sh[];
    __half* sWhi = sh;             // [128][WSTR]

    const int tid  = threadIdx.x;
    const int wid  = tid >> 5;
    const int lane = tid & 31;
    const int wm   = wid & 3;      // 0..3  (m sub-tile, 32 rows)
    const int wn   = wid >> 2;     // 0..3  (n sub-tile, 32 cols)
    const int n0   = blockIdx.x * 128;

    const int fr = lane >> 2;      // 0..7
    const int fc = (lane & 3) * 2; // 0,2,4,6

    // ---- Stage W_hi slice (once per CTA) ----
    for (int idx = tid; idx < 128 * KP; idx += 512) {
        int r = idx / KP, k = idx - r * KP;
        float v = (k < Isz) ? W[(size_t)(n0 + r) * Isz + k] : 0.f;
        sWhi[r * WSTR + k] = __float2half_rn(v);
    }
    __syncthreads();

    // ---- Bias (depends only on n) ----
    float bi0[4], bi1[4];
#pragma unroll
    for (int nt = 0; nt < 4; ++nt) {
        int n = n0 + wn * 32 + nt * 8 + fc;
        bi0[nt] = b_ih[n] + b_hh[n];
        bi1[nt] = b_ih[n + 1] + b_hh[n + 1];
    }

    for (int it = 0; it < 4; ++it) {
        const int m0 = (blockIdx.y + 256 * it) * 128;
        const int mb = m0 + wm * 32;

        float acc[2][4][4];
#pragma unroll
        for (int mt = 0; mt < 2; ++mt)
#pragma unroll
            for (int nt = 0; nt < 4; ++nt)
#pragma unroll
                for (int q = 0; q < 4; ++q) acc[mt][nt][q] = 0.f;

        // A fragment double buffer: [buf][mt][reg]
        u32 Ah[2][2][4], Al[2][2][4];

        // proven layout: a0=(row fr, k fc), a1=row+8, a2=k+8, a3=row+8,k+8
#define LOADA(BUF, K0)                                                        \
        {                                                                     \
            _Pragma("unroll")                                                 \
            for (int mt = 0; mt < 2; ++mt) {                                  \
                size_t base = (size_t)(mb + mt * 16 + fr) * KP + (K0) + fc;   \
                Ah[BUF][mt][0] = *(const u32*)(g_xhi + base);                 \
                Ah[BUF][mt][1] = *(const u32*)(g_xhi + base + 8 * KP);        \
                Ah[BUF][mt][2] = *(const u32*)(g_xhi + base + 8);             \
                Ah[BUF][mt][3] = *(const u32*)(g_xhi + base + 8 * KP + 8);    \
                Al[BUF][mt][0] = *(const u32*)(g_xlo + base);                 \
                Al[BUF][mt][1] = *(const u32*)(g_xlo + base + 8 * KP);        \
                Al[BUF][mt][2] = *(const u32*)(g_xlo + base + 8);             \
                Al[BUF][mt][3] = *(const u32*)(g_xlo + base + 8 * KP + 8);    \
            }                                                                 \
        }

        LOADA(0, 0)

        for (int kk = 0; kk < 20; ++kk) {
            const int cur = kk & 1;
            const int nxt = cur ^ 1;
            if (kk < 19) LOADA(nxt, (kk + 1) * 16)

            const int k0 = kk * 16;
            const __half* bbase = sWhi + (wn * 32 + fr) * WSTR + k0 + fc;
#pragma unroll
            for (int nt = 0; nt < 4; ++nt) {
                const __half* bph = bbase + nt * 8 * WSTR;
                u32 bh0 = *(const u32*)bph;
                u32 bh1 = *(const u32*)(bph + 8);
                // hi*hi
                mma16816(acc[0][nt][0], acc[0][nt][1], acc[0][nt][2], acc[0][nt][3],
                         Ah[cur][0][0], Ah[cur][0][1], Ah[cur][0][2], Ah[cur][0][3], bh0, bh1);
                mma16816(acc[1][nt][0], acc[1][nt][1], acc[1][nt][2], acc[1][nt][3],
                         Ah[cur][1][0], Ah[cur][1][1], Ah[cur][1][2], Ah[cur][1][3], bh0, bh1);
                // lo*hi
                mma16816(acc[0][nt][0], acc[0][nt][1], acc[0][nt][2], acc[0][nt][3],
                         Al[cur][0][0], Al[cur][0][1], Al[cur][0][2], Al[cur][0][3], bh0, bh1);
                mma16816(acc[1][nt][0], acc[1][nt][1], acc[1][nt][2], acc[1][nt][3],
                         Al[cur][1][0], Al[cur][1][1], Al[cur][1][2], Al[cur][1][3], bh0, bh1);
            }
        }
#undef LOADA

        // ---- Epilogue (proven accumulator mapping) ----
#pragma unroll
        for (int mt = 0; mt < 2; ++mt) {
            int m = mb + mt * 16 + fr;
            float* dst0 = g_xg + (size_t)m * G4 + n0 + wn * 32;
            float* dst1 = dst0 + (size_t)8 * G4;    // row m+8
#pragma unroll
            for (int nt = 0; nt < 4; ++nt) {
                float2 v0 = make_float2(acc[mt][nt][0] + bi0[nt], acc[mt][nt][1] + bi1[nt]);
                float2 v1 = make_float2(acc[mt][nt][2] + bi0[nt], acc[mt][nt][3] + bi1[nt]);
                *(float2*)(dst0 + nt * 8 + fc) = v0;
                *(float2*)(dst1 + nt * 8 + fc) = v1;
            }
        }
    }
}

// ----------------------------------------------------------------------------
// Kernel 2: recurrence with register-resident fp16 W_hh via mma.sync m16n8k16.
// (unchanged — proven at rel_err 3.6e-5)
// ----------------------------------------------------------------------------
#define ROWS 2

__global__ __launch_bounds__(512, 1)
void lstm_fc_kernel(const float* __restrict__ W_hh,   // [512,128]
                    const float* __restrict__ fc_w,   // [1,128]
                    const float* __restrict__ fc_b,   // [1]
                    float* __restrict__ out) {        // [256]
    __shared__ __align__(16) ull  sFrag[8 * 32];
    __shared__ float sG[ROWS * G4];
    __shared__ float sH[ROWS * Hsz];
    __shared__ float sXG[2][ROWS * G4];

    const int tid  = threadIdx.x;
    const int wid  = tid >> 5;
    const int lane = tid & 31;
    const int b0   = blockIdx.x * ROWS;
    const int wbase = wid * 32;

    u32 wa[8][2][4];
    {
        const int mrow = lane >> 2;
        const int kcol = (lane & 3) * 2;
#pragma unroll
        for (int kc = 0; kc < 8; ++kc) {
#pragma unroll
            for (int mt = 0; mt < 2; ++mt) {
                int r0 = wbase + mt * 16 + mrow;
                int k0 = kc * 16 + kcol;
                float2 w00 = *(const float2*)(W_hh + (size_t)r0 * Hsz + k0);
                float2 w10 = *(const float2*)(W_hh + (size_t)(r0 + 8) * Hsz + k0);
                float2 w01 = *(const float2*)(W_hh + (size_t)r0 * Hsz + k0 + 8);
                float2 w11 = *(const float2*)(W_hh + (size_t)(r0 + 8) * Hsz + k0 + 8);
                wa[kc][mt][0] = packh2(w00.x, w00.y);
                wa[kc][mt][1] = packh2(w10.x, w10.y);
                wa[kc][mt][2] = packh2(w01.x, w01.y);
                wa[kc][mt][3] = packh2(w11.x, w11.y);
            }
        }
    }

    if (tid < 256) sFrag[tid] = 0ull;
    if (tid < ROWS * Hsz) sH[tid] = 0.f;
    {
        int r = tid >> 8;
        int off = (tid & 255) * 2;
        float2 v = *(const float2*)(g_xg + (((size_t)(b0 + r)) * Tsz + 0) * G4 + off);
        sXG[0][r * G4 + off]     = v.x;
        sXG[0][r * G4 + off + 1] = v.y;
    }

    float cst = 0.f;
    const int r2 = tid >> 7;
    const int n2 = tid & 127;

    const bool act_lane = ((lane & 3) == 0);
    const int mrow_act = lane >> 2;
    const int gate = wid >> 2;

    __syncthreads();

    int buf = 0;
    for (int t = 0; t < Tsz; ++t) {
        float c0[4] = {0.f, 0.f, 0.f, 0.f};
        float c1[4] = {0.f, 0.f, 0.f, 0.f};
#pragma unroll
        for (int kc = 0; kc < 8; ++kc) {
            ull bv = sFrag[kc * 32 + lane];
            u32 b0r = (u32)bv;
            u32 b1r = (u32)(bv >> 32);
            mma16816(c0[0], c0[1], c0[2], c0[3],
                     wa[kc][0][0], wa[kc][0][1], wa[kc][0][2], wa[kc][0][3], b0r, b1r);
            mma16816(c1[0], c1[1], c1[2], c1[3],
                     wa[kc][1][0], wa[kc][1][1], wa[kc][1][2], wa[kc][1][3], b0r, b1r);
        }

        float2 xnext = make_float2(0.f, 0.f);
        int roff, coff;
        {
            roff = tid >> 8;
            coff = (tid & 255) * 2;
            if (t + 1 < Tsz)
                xnext = *(const float2*)(g_xg + (((size_t)(b0 + roff)) * Tsz + (t + 1)) * G4 + coff);
        }

        if (act_lane) {
#pragma unroll
            for (int mt = 0; mt < 2; ++mt) {
                float* cc = (mt == 0) ? c0 : c1;
                int mlow = wbase + mt * 16 + mrow_act;
                float v00 = cc[0] + sXG[buf][mlow];
                float v01 = cc[1] + sXG[buf][G4 + mlow];
                float v10 = cc[2] + sXG[buf][mlow + 8];
                float v11 = cc[3] + sXG[buf][G4 + mlow + 8];
                if (gate == 2) {
                    v00 = __tanhf(v00); v01 = __tanhf(v01);
                    v10 = __tanhf(v10); v11 = __tanhf(v11);
                } else {
                    v00 = sigmoid_fast(v00); v01 = sigmoid_fast(v01);
                    v10 = sigmoid_fast(v10); v11 = sigmoid_fast(v11);
                }
                sG[mlow]           = v00;
                sG[G4 + mlow]      = v01;
                sG[mlow + 8]       = v10;
                sG[G4 + mlow + 8]  = v11;
            }
        }

        sXG[buf ^ 1][roff * G4 + coff]     = xnext.x;
        sXG[buf ^ 1][roff * G4 + coff + 1] = xnext.y;

        __syncthreads();

        if (tid < 256) {
            float iv = sG[r2 * G4 + n2];
            float fv = sG[r2 * G4 + 128 + n2];
            float gv = sG[r2 * G4 + 256 + n2];
            float ov = sG[r2 * G4 + 384 + n2];
            cst = fv * cst + iv * gv;
            float h = ov * __tanhf(cst);
            sH[r2 * Hsz + n2] = h;
            int kc   = n2 >> 4;
            int kw   = n2 & 15;
            int reg  = (kw >> 3) & 1;
            int ln   = 4 * r2 + ((kw & 7) >> 1);
            __half* fr = (__half*)&sFrag[kc * 32 + ln];
            fr[reg * 2 + (kw & 1)] = __float2half_rn(h);
        }
        __syncthreads();
        buf ^= 1;
    }

    if (tid < ROWS) {
        float s = 0.f;
#pragma unroll 8
        for (int k = 0; k < Hsz; ++k) s += sH[tid * Hsz + k] * fc_w[k];
        out[b0 + tid] = s + fc_b[0];
    }
}

// ----------------------------------------------------------------------------
// Launch
// ----------------------------------------------------------------------------
extern "C" void kernel_launch(void* const* d_in, const int* in_sizes, int n_in,
                              void* d_out, int out_size) {
    const float* x    = (const float*)d_in[0];
    const float* W_ih = (const float*)d_in[1];
    const float* W_hh = (const float*)d_in[2];
    const float* b_ih = (const float*)d_in[3];
    const float* b_hh = (const float*)d_in[4];
    const float* fc_w = (const float*)d_in[5];
    const float* fc_b = (const float*)d_in[6];
    float* out = (float*)d_out;

    // Kernel 0: x -> fp16 hi/lo (padded), vectorized
    size_t total = (size_t)Msz * CVT_TPR;
    convert_x<<<(unsigned)((total + 255) / 256), 256>>>(x);

    // Kernel 1: tensor-core split GEMM (2-pass)
    cudaFuncSetAttribute(gemm_xg_tc2,
                         cudaFuncAttributeMaxDynamicSharedMemorySize, SMEM_GEMM);
    gemm_xg_tc2<<<dim3(4, 256), 512, SMEM_GEMM>>>(W_ih, b_ih, b_hh);

    // Kernel 2: persistent recurrence + fused FC
    lstm_fc_kernel<<<Bsz / ROWS, 512>>>(W_hh, fc_w, fc_b, out);
}